// round 1
// baseline (speedup 1.0000x reference)
#include <cuda_runtime.h>
#include <cstddef>

// Problem constants (fixed by reference setup_inputs)
#define N_SRC   16384
#define N_TGT   65536
#define KNBR    8
#define CCH     16      // mv channels
#define CSKIP   2
#define SSC     32      // scalars
#define HID     64
#define MVD     16      // multivector blade dim
#define ROW_MV  (CCH*MVD)        // 256 floats per mv_src row
#define TPB     256
#define TGT_PER_BLOCK 16
#define MV_STRIDE 304            // stride == 16 (mod 32) words -> conflict-free phase 2
#define SC_STRIDE 68

__device__ float g_Weff[(CCH + CSKIP) * CCH];   // 18x16 fused mv weight

// ---------------------------------------------------------------------------
// Prep kernel: Weff[c',c] = sum_h W1_mv[c',h] * W2_mv[h,c]   (18x16 = 288)
// ---------------------------------------------------------------------------
__global__ void prep_weff(const float* __restrict__ W1_mv,
                          const float* __restrict__ W2_mv)
{
    int idx = threadIdx.x;
    if (idx < (CCH + CSKIP) * CCH) {
        int cp = idx >> 4;
        int c  = idx & 15;
        float acc = 0.f;
        #pragma unroll
        for (int h = 0; h < HID; h++)
            acc = fmaf(W1_mv[cp * HID + h], W2_mv[h * CCH + c], acc);
        g_Weff[idx] = acc;
    }
}

__device__ __forceinline__ float gelu_tanh(float x)
{
    // jax.nn.gelu approximate=True (tanh form)
    const float c0 = 0.7978845608028654f;
    float u = c0 * fmaf(0.044715f * x, x * x, x);
    float t = tanhf(u);
    return 0.5f * x * (1.0f + t);
}

// ---------------------------------------------------------------------------
// Fused main kernel: IDW interp + concat + (fused) mv linear + scalar MLP
// ---------------------------------------------------------------------------
__global__ __launch_bounds__(TPB) void fused_kernel(
    const float* __restrict__ mv_src,  const float* __restrict__ mv_skip,
    const float* __restrict__ sc_src,  const float* __restrict__ sc_skip,
    const float* __restrict__ pos_src, const float* __restrict__ pos_tgt,
    const int*   __restrict__ isrc,
    const float* __restrict__ W1_s,    const float* __restrict__ b1_s,
    const float* __restrict__ W2_s,    const float* __restrict__ b2_s,
    float* __restrict__ out_mv,        float* __restrict__ out_sc)
{
    __shared__ __align__(16) float sW1[HID * HID];                  // 16 KB
    __shared__ __align__(16) float sWe[(CCH + CSKIP) * CCH];        // 1.1 KB
    __shared__ __align__(16) float sMV[TGT_PER_BLOCK * MV_STRIDE];  // 19 KB
    __shared__ __align__(16) float sSC[TGT_PER_BLOCK * SC_STRIDE];  // 4.25 KB
    __shared__ __align__(16) float sH [TGT_PER_BLOCK * SC_STRIDE];  // 4.25 KB

    const int tid  = threadIdx.x;
    const int lane = tid & 31;
    const int warp = tid >> 5;
    const int tbase = blockIdx.x * TGT_PER_BLOCK;

    // Stage weights
    for (int i = tid; i < HID * HID; i += TPB) sW1[i] = W1_s[i];
    for (int i = tid; i < (CCH + CSKIP) * CCH; i += TPB) sWe[i] = g_Weff[i];

    // ---------------- Phase 1: IDW interpolation (warp per target, x2) ------
    #pragma unroll
    for (int u = 0; u < 2; u++) {
        const int tl = warp * 2 + u;
        const int t  = tbase + tl;

        float wk = 0.f;
        int   sk = 0;
        if (lane < KNBR) {
            sk = isrc[t * KNBR + lane];
            float dx = pos_src[sk * 3 + 0] - pos_tgt[t * 3 + 0];
            float dy = pos_src[sk * 3 + 1] - pos_tgt[t * 3 + 1];
            float dz = pos_src[sk * 3 + 2] - pos_tgt[t * 3 + 2];
            float d2 = fmaf(dx, dx, fmaf(dy, dy, dz * dz));
            d2 = fmaxf(d2, 1e-16f);
            wk = 1.0f / d2;
        }
        float den = wk;
        #pragma unroll
        for (int o = 16; o; o >>= 1) den += __shfl_xor_sync(0xffffffffu, den, o);
        const float invd = 1.0f / den;

        float4 a0 = make_float4(0.f, 0.f, 0.f, 0.f);
        float4 a1 = make_float4(0.f, 0.f, 0.f, 0.f);
        float  sacc = 0.f;
        #pragma unroll
        for (int k = 0; k < KNBR; k++) {
            const float w = __shfl_sync(0xffffffffu, wk, k);
            const int   s = __shfl_sync(0xffffffffu, sk, k);
            const float4* row = (const float4*)(mv_src + (size_t)s * ROW_MV);
            float4 v0 = __ldg(row + lane);
            float4 v1 = __ldg(row + lane + 32);
            a0.x = fmaf(w, v0.x, a0.x); a0.y = fmaf(w, v0.y, a0.y);
            a0.z = fmaf(w, v0.z, a0.z); a0.w = fmaf(w, v0.w, a0.w);
            a1.x = fmaf(w, v1.x, a1.x); a1.y = fmaf(w, v1.y, a1.y);
            a1.z = fmaf(w, v1.z, a1.z); a1.w = fmaf(w, v1.w, a1.w);
            sacc = fmaf(w, __ldg(sc_src + (size_t)s * SSC + lane), sacc);
        }
        a0.x *= invd; a0.y *= invd; a0.z *= invd; a0.w *= invd;
        a1.x *= invd; a1.y *= invd; a1.z *= invd; a1.w *= invd;

        float4* mrow = (float4*)(sMV + tl * MV_STRIDE);
        mrow[lane]      = a0;
        mrow[lane + 32] = a1;
        sMV[tl * MV_STRIDE + 256 + lane] = mv_skip[(size_t)t * (CSKIP * MVD) + lane];
        sSC[tl * SC_STRIDE + lane]       = sacc * invd;
        sSC[tl * SC_STRIDE + 32 + lane]  = sc_skip[(size_t)t * SSC + lane];
    }
    __syncthreads();

    // ---------------- Phase 2: mv output (fused linear with Weff) -----------
    {
        const int tl = tid >> 4;
        const int i  = tid & 15;
        const float* mvc = sMV + tl * MV_STRIDE + i;
        float o[16];
        #pragma unroll
        for (int c = 0; c < 16; c++) o[c] = 0.f;
        #pragma unroll
        for (int cp = 0; cp < CCH + CSKIP; cp++) {
            const float m = mvc[cp * 16];
            const float4* wr = (const float4*)(sWe + cp * 16);
            float4 w0 = wr[0], w1 = wr[1], w2 = wr[2], w3 = wr[3];
            o[0]  = fmaf(m, w0.x, o[0]);  o[1]  = fmaf(m, w0.y, o[1]);
            o[2]  = fmaf(m, w0.z, o[2]);  o[3]  = fmaf(m, w0.w, o[3]);
            o[4]  = fmaf(m, w1.x, o[4]);  o[5]  = fmaf(m, w1.y, o[5]);
            o[6]  = fmaf(m, w1.z, o[6]);  o[7]  = fmaf(m, w1.w, o[7]);
            o[8]  = fmaf(m, w2.x, o[8]);  o[9]  = fmaf(m, w2.y, o[9]);
            o[10] = fmaf(m, w2.z, o[10]); o[11] = fmaf(m, w2.w, o[11]);
            o[12] = fmaf(m, w3.x, o[12]); o[13] = fmaf(m, w3.y, o[13]);
            o[14] = fmaf(m, w3.z, o[14]); o[15] = fmaf(m, w3.w, o[15]);
        }
        float* dst = out_mv + (size_t)(tbase + tl) * ROW_MV + i;
        #pragma unroll
        for (int c = 0; c < 16; c++) dst[c * 16] = o[c];
    }

    // ---------------- Phase 3a: scalar hidden layer + gelu ------------------
    {
        const int tl = tid >> 4;
        const int h4 = (tid & 15) * 4;
        float4 bb = *(const float4*)(b1_s + h4);
        float acc0 = bb.x, acc1 = bb.y, acc2 = bb.z, acc3 = bb.w;
        const float* xrow = sSC + tl * SC_STRIDE;
        #pragma unroll
        for (int jc = 0; jc < 16; jc++) {
            float4 xv = *(const float4*)(xrow + 4 * jc);
            const float* wb = sW1 + (4 * jc) * HID + h4;
            float4 wa0 = *(const float4*)(wb);
            float4 wa1 = *(const float4*)(wb + HID);
            float4 wa2 = *(const float4*)(wb + 2 * HID);
            float4 wa3 = *(const float4*)(wb + 3 * HID);
            acc0 = fmaf(xv.x, wa0.x, acc0); acc1 = fmaf(xv.x, wa0.y, acc1);
            acc2 = fmaf(xv.x, wa0.z, acc2); acc3 = fmaf(xv.x, wa0.w, acc3);
            acc0 = fmaf(xv.y, wa1.x, acc0); acc1 = fmaf(xv.y, wa1.y, acc1);
            acc2 = fmaf(xv.y, wa1.z, acc2); acc3 = fmaf(xv.y, wa1.w, acc3);
            acc0 = fmaf(xv.z, wa2.x, acc0); acc1 = fmaf(xv.z, wa2.y, acc1);
            acc2 = fmaf(xv.z, wa2.z, acc2); acc3 = fmaf(xv.z, wa2.w, acc3);
            acc0 = fmaf(xv.w, wa3.x, acc0); acc1 = fmaf(xv.w, wa3.y, acc1);
            acc2 = fmaf(xv.w, wa3.z, acc2); acc3 = fmaf(xv.w, wa3.w, acc3);
        }
        acc0 = gelu_tanh(acc0); acc1 = gelu_tanh(acc1);
        acc2 = gelu_tanh(acc2); acc3 = gelu_tanh(acc3);
        *(float4*)(sH + tl * SC_STRIDE + h4) = make_float4(acc0, acc1, acc2, acc3);
    }
    __syncwarp();

    // ---------------- Phase 3b: scalar output layer --------------------------
    {
        const int tl = tid >> 4;
        const int c2 = (tid & 15) * 2;
        float2 bb = *(const float2*)(b2_s + c2);
        float a0 = bb.x, a1 = bb.y;
        const float* hrow = sH + tl * SC_STRIDE;
        #pragma unroll
        for (int hc = 0; hc < 16; hc++) {
            float4 hv = *(const float4*)(hrow + 4 * hc);
            const float* wb = W2_s + (4 * hc) * SSC + c2;   // L1-resident (8 KB)
            float2 wa0 = __ldg((const float2*)(wb));
            float2 wa1 = __ldg((const float2*)(wb + SSC));
            float2 wa2 = __ldg((const float2*)(wb + 2 * SSC));
            float2 wa3 = __ldg((const float2*)(wb + 3 * SSC));
            a0 = fmaf(hv.x, wa0.x, a0); a1 = fmaf(hv.x, wa0.y, a1);
            a0 = fmaf(hv.y, wa1.x, a0); a1 = fmaf(hv.y, wa1.y, a1);
            a0 = fmaf(hv.z, wa2.x, a0); a1 = fmaf(hv.z, wa2.y, a1);
            a0 = fmaf(hv.w, wa3.x, a0); a1 = fmaf(hv.w, wa3.y, a1);
        }
        float2* dst = (float2*)(out_sc + (size_t)(tbase + tl) * SSC + c2);
        *dst = make_float2(a0, a1);
    }
}

// ---------------------------------------------------------------------------
extern "C" void kernel_launch(void* const* d_in, const int* in_sizes, int n_in,
                              void* d_out, int out_size)
{
    const float* mv_src   = (const float*)d_in[0];
    const float* mv_skip  = (const float*)d_in[1];
    const float* sc_src   = (const float*)d_in[2];
    const float* sc_skip  = (const float*)d_in[3];
    const float* pos_src  = (const float*)d_in[4];
    const float* pos_tgt  = (const float*)d_in[5];
    const int*   isrc     = (const int*)d_in[6];
    // d_in[7] = interp_target: structurally repeat(arange(N_TGT), K) — unused
    const float* W1_mv    = (const float*)d_in[8];
    const float* W2_mv    = (const float*)d_in[9];
    const float* W1_s     = (const float*)d_in[10];
    const float* b1_s     = (const float*)d_in[11];
    const float* W2_s     = (const float*)d_in[12];
    const float* b2_s     = (const float*)d_in[13];

    float* out_mv = (float*)d_out;
    float* out_sc = out_mv + (size_t)N_TGT * CCH * MVD;   // tuple order: mv_o, sc_o

    prep_weff<<<1, 288>>>(W1_mv, W2_mv);
    fused_kernel<<<N_TGT / TGT_PER_BLOCK, TPB>>>(
        mv_src, mv_skip, sc_src, sc_skip, pos_src, pos_tgt, isrc,
        W1_s, b1_s, W2_s, b2_s, out_mv, out_sc);
}

// round 2
// speedup vs baseline: 1.4371x; 1.4371x over previous
#include <cuda_runtime.h>
#include <cstddef>

#define N_SRC   16384
#define N_TGT   65536
#define KNBR    8
#define CCH     16
#define CSKIP   2
#define SSC     32
#define HID     64
#define MVD     16
#define ROW_MV  (CCH*MVD)
#define TPB     128
#define TGT_PER_BLOCK 16
#define MV_STRIDE 296     // mod 32 = 8, 2*stride mod 32 = 16 -> conflict-free phase-2 m loads
#define SC_STRIDE 68      // multiple of 4 (float4 alignment); row writes lane-consecutive

__device__ float g_Weff[(CCH + CSKIP) * CCH];

// ---------------------------------------------------------------------------
__global__ void prep_weff(const float* __restrict__ W1_mv,
                          const float* __restrict__ W2_mv)
{
    int idx = threadIdx.x;
    if (idx < (CCH + CSKIP) * CCH) {
        int cp = idx >> 4;
        int c  = idx & 15;
        float acc = 0.f;
        #pragma unroll
        for (int h = 0; h < HID; h++)
            acc = fmaf(W1_mv[cp * HID + h], W2_mv[h * CCH + c], acc);
        g_Weff[idx] = acc;
    }
}

__device__ __forceinline__ float gelu_tanh(float x)
{
    const float c0 = 0.7978845608028654f;
    float u = c0 * fmaf(0.044715f * x, x * x, x);
    float t = tanhf(u);
    return 0.5f * x * (1.0f + t);
}

// ---------------------------------------------------------------------------
__global__ __launch_bounds__(TPB, 6) void fused_kernel(
    const float* __restrict__ mv_src,  const float* __restrict__ mv_skip,
    const float* __restrict__ sc_src,  const float* __restrict__ sc_skip,
    const float* __restrict__ pos_src, const float* __restrict__ pos_tgt,
    const int*   __restrict__ isrc,
    const float* __restrict__ W1_s,    const float* __restrict__ b1_s,
    const float* __restrict__ W2_s,    const float* __restrict__ b2_s,
    float* __restrict__ out_mv,        float* __restrict__ out_sc)
{
    __shared__ __align__(16) float sWe[(CCH + CSKIP) * CCH];        // 1.1 KB
    __shared__ __align__(16) float sMV[TGT_PER_BLOCK * MV_STRIDE];  // 18.5 KB
    __shared__ __align__(16) float sSC[TGT_PER_BLOCK * SC_STRIDE];  // 4.25 KB
    __shared__ __align__(16) float sH [TGT_PER_BLOCK * SC_STRIDE];  // 4.25 KB

    const int tid  = threadIdx.x;
    const int lane = tid & 31;
    const int warp = tid >> 5;               // 0..3
    const int tbase = blockIdx.x * TGT_PER_BLOCK;

    for (int i = tid; i < (CCH + CSKIP) * CCH; i += TPB) sWe[i] = g_Weff[i];

    // ---------------- Phase 1: IDW interpolation (warp per target, x4) ------
    #pragma unroll
    for (int u = 0; u < 4; u++) {
        const int tl = warp * 4 + u;
        const int t  = tbase + tl;

        float wk = 0.f;
        int   sk = 0;
        if (lane < KNBR) {
            sk = isrc[t * KNBR + lane];
            float dx = pos_src[sk * 3 + 0] - pos_tgt[t * 3 + 0];
            float dy = pos_src[sk * 3 + 1] - pos_tgt[t * 3 + 1];
            float dz = pos_src[sk * 3 + 2] - pos_tgt[t * 3 + 2];
            float d2 = fmaf(dx, dx, fmaf(dy, dy, dz * dz));
            d2 = fmaxf(d2, 1e-16f);
            wk = 1.0f / d2;
        }
        float den = wk;
        #pragma unroll
        for (int o = 16; o; o >>= 1) den += __shfl_xor_sync(0xffffffffu, den, o);
        const float invd = 1.0f / den;

        float4 a0 = make_float4(0.f, 0.f, 0.f, 0.f);
        float4 a1 = make_float4(0.f, 0.f, 0.f, 0.f);
        float  sacc = 0.f;
        #pragma unroll
        for (int k = 0; k < KNBR; k++) {
            const float w = __shfl_sync(0xffffffffu, wk, k);
            const int   s = __shfl_sync(0xffffffffu, sk, k);
            const float4* row = (const float4*)(mv_src + (size_t)s * ROW_MV);
            float4 v0 = __ldg(row + lane);
            float4 v1 = __ldg(row + lane + 32);
            a0.x = fmaf(w, v0.x, a0.x); a0.y = fmaf(w, v0.y, a0.y);
            a0.z = fmaf(w, v0.z, a0.z); a0.w = fmaf(w, v0.w, a0.w);
            a1.x = fmaf(w, v1.x, a1.x); a1.y = fmaf(w, v1.y, a1.y);
            a1.z = fmaf(w, v1.z, a1.z); a1.w = fmaf(w, v1.w, a1.w);
            sacc = fmaf(w, __ldg(sc_src + (size_t)s * SSC + lane), sacc);
        }
        a0.x *= invd; a0.y *= invd; a0.z *= invd; a0.w *= invd;
        a1.x *= invd; a1.y *= invd; a1.z *= invd; a1.w *= invd;

        float4* mrow = (float4*)(sMV + tl * MV_STRIDE);
        mrow[lane]      = a0;
        mrow[lane + 32] = a1;
        sMV[tl * MV_STRIDE + 256 + lane] = mv_skip[(size_t)t * (CSKIP * MVD) + lane];
        sSC[tl * SC_STRIDE + lane]       = sacc * invd;
        sSC[tl * SC_STRIDE + 32 + lane]  = sc_skip[(size_t)t * SSC + lane];
    }
    __syncthreads();

    const int tp  = tid >> 4;          // 0..7 -> target pair
    const int sub = tid & 15;
    const int tlA = tp * 2;
    const int tlB = tp * 2 + 1;

    // ---------------- Phase 2: mv output (fused Weff), 2 targets/thread -----
    {
        const int i = sub;             // blade index
        const float* mA = sMV + tlA * MV_STRIDE + i;
        const float* mB = sMV + tlB * MV_STRIDE + i;
        float oa[16], ob[16];
        #pragma unroll
        for (int c = 0; c < 16; c++) { oa[c] = 0.f; ob[c] = 0.f; }
        #pragma unroll
        for (int cp = 0; cp < CCH + CSKIP; cp++) {
            const float ma = mA[cp * 16];
            const float mb = mB[cp * 16];
            const float4* wr = (const float4*)(sWe + cp * 16);
            float4 w0 = wr[0], w1 = wr[1], w2 = wr[2], w3 = wr[3];
            oa[0]  = fmaf(ma, w0.x, oa[0]);  ob[0]  = fmaf(mb, w0.x, ob[0]);
            oa[1]  = fmaf(ma, w0.y, oa[1]);  ob[1]  = fmaf(mb, w0.y, ob[1]);
            oa[2]  = fmaf(ma, w0.z, oa[2]);  ob[2]  = fmaf(mb, w0.z, ob[2]);
            oa[3]  = fmaf(ma, w0.w, oa[3]);  ob[3]  = fmaf(mb, w0.w, ob[3]);
            oa[4]  = fmaf(ma, w1.x, oa[4]);  ob[4]  = fmaf(mb, w1.x, ob[4]);
            oa[5]  = fmaf(ma, w1.y, oa[5]);  ob[5]  = fmaf(mb, w1.y, ob[5]);
            oa[6]  = fmaf(ma, w1.z, oa[6]);  ob[6]  = fmaf(mb, w1.z, ob[6]);
            oa[7]  = fmaf(ma, w1.w, oa[7]);  ob[7]  = fmaf(mb, w1.w, ob[7]);
            oa[8]  = fmaf(ma, w2.x, oa[8]);  ob[8]  = fmaf(mb, w2.x, ob[8]);
            oa[9]  = fmaf(ma, w2.y, oa[9]);  ob[9]  = fmaf(mb, w2.y, ob[9]);
            oa[10] = fmaf(ma, w2.z, oa[10]); ob[10] = fmaf(mb, w2.z, ob[10]);
            oa[11] = fmaf(ma, w2.w, oa[11]); ob[11] = fmaf(mb, w2.w, ob[11]);
            oa[12] = fmaf(ma, w3.x, oa[12]); ob[12] = fmaf(mb, w3.x, ob[12]);
            oa[13] = fmaf(ma, w3.y, oa[13]); ob[13] = fmaf(mb, w3.y, ob[13]);
            oa[14] = fmaf(ma, w3.z, oa[14]); ob[14] = fmaf(mb, w3.z, ob[14]);
            oa[15] = fmaf(ma, w3.w, oa[15]); ob[15] = fmaf(mb, w3.w, ob[15]);
        }
        float* dA = out_mv + (size_t)(tbase + tlA) * ROW_MV + i;
        float* dB = out_mv + (size_t)(tbase + tlB) * ROW_MV + i;
        #pragma unroll
        for (int c = 0; c < 16; c++) { dA[c * 16] = oa[c]; dB[c * 16] = ob[c]; }
    }

    // ---------------- Phase 3a: scalar hidden + gelu, 2 targets/thread ------
    {
        const int h4 = sub * 4;
        float4 bb = __ldg((const float4*)(b1_s + h4));
        float a0 = bb.x, a1 = bb.y, a2 = bb.z, a3 = bb.w;
        float b0 = bb.x, b1 = bb.y, b2 = bb.z, b3 = bb.w;
        const float* xA = sSC + tlA * SC_STRIDE;
        const float* xB = sSC + tlB * SC_STRIDE;
        #pragma unroll
        for (int jc = 0; jc < 16; jc++) {
            float4 xa = *(const float4*)(xA + 4 * jc);
            float4 xb = *(const float4*)(xB + 4 * jc);
            const float* wb = W1_s + (4 * jc) * HID + h4;
            float4 w0 = __ldg((const float4*)(wb));
            float4 w1 = __ldg((const float4*)(wb + HID));
            float4 w2 = __ldg((const float4*)(wb + 2 * HID));
            float4 w3 = __ldg((const float4*)(wb + 3 * HID));
            a0 = fmaf(xa.x, w0.x, a0); a1 = fmaf(xa.x, w0.y, a1);
            a2 = fmaf(xa.x, w0.z, a2); a3 = fmaf(xa.x, w0.w, a3);
            b0 = fmaf(xb.x, w0.x, b0); b1 = fmaf(xb.x, w0.y, b1);
            b2 = fmaf(xb.x, w0.z, b2); b3 = fmaf(xb.x, w0.w, b3);
            a0 = fmaf(xa.y, w1.x, a0); a1 = fmaf(xa.y, w1.y, a1);
            a2 = fmaf(xa.y, w1.z, a2); a3 = fmaf(xa.y, w1.w, a3);
            b0 = fmaf(xb.y, w1.x, b0); b1 = fmaf(xb.y, w1.y, b1);
            b2 = fmaf(xb.y, w1.z, b2); b3 = fmaf(xb.y, w1.w, b3);
            a0 = fmaf(xa.z, w2.x, a0); a1 = fmaf(xa.z, w2.y, a1);
            a2 = fmaf(xa.z, w2.z, a2); a3 = fmaf(xa.z, w2.w, a3);
            b0 = fmaf(xb.z, w2.x, b0); b1 = fmaf(xb.z, w2.y, b1);
            b2 = fmaf(xb.z, w2.z, b2); b3 = fmaf(xb.z, w2.w, b3);
            a0 = fmaf(xa.w, w3.x, a0); a1 = fmaf(xa.w, w3.y, a1);
            a2 = fmaf(xa.w, w3.z, a2); a3 = fmaf(xa.w, w3.w, a3);
            b0 = fmaf(xb.w, w3.x, b0); b1 = fmaf(xb.w, w3.y, b1);
            b2 = fmaf(xb.w, w3.z, b2); b3 = fmaf(xb.w, w3.w, b3);
        }
        *(float4*)(sH + tlA * SC_STRIDE + h4) =
            make_float4(gelu_tanh(a0), gelu_tanh(a1), gelu_tanh(a2), gelu_tanh(a3));
        *(float4*)(sH + tlB * SC_STRIDE + h4) =
            make_float4(gelu_tanh(b0), gelu_tanh(b1), gelu_tanh(b2), gelu_tanh(b3));
    }
    __syncwarp();

    // ---------------- Phase 3b: scalar output, 2 targets/thread -------------
    {
        const int c2 = sub * 2;
        float2 bb = __ldg((const float2*)(b2_s + c2));
        float a0 = bb.x, a1 = bb.y;
        float b0 = bb.x, b1 = bb.y;
        const float* hA = sH + tlA * SC_STRIDE;
        const float* hB = sH + tlB * SC_STRIDE;
        #pragma unroll
        for (int hc = 0; hc < 16; hc++) {
            float4 ha = *(const float4*)(hA + 4 * hc);
            float4 hb = *(const float4*)(hB + 4 * hc);
            const float* wb = W2_s + (4 * hc) * SSC + c2;
            float2 w0 = __ldg((const float2*)(wb));
            float2 w1 = __ldg((const float2*)(wb + SSC));
            float2 w2 = __ldg((const float2*)(wb + 2 * SSC));
            float2 w3 = __ldg((const float2*)(wb + 3 * SSC));
            a0 = fmaf(ha.x, w0.x, a0); a1 = fmaf(ha.x, w0.y, a1);
            b0 = fmaf(hb.x, w0.x, b0); b1 = fmaf(hb.x, w0.y, b1);
            a0 = fmaf(ha.y, w1.x, a0); a1 = fmaf(ha.y, w1.y, a1);
            b0 = fmaf(hb.y, w1.x, b0); b1 = fmaf(hb.y, w1.y, b1);
            a0 = fmaf(ha.z, w2.x, a0); a1 = fmaf(ha.z, w2.y, a1);
            b0 = fmaf(hb.z, w2.x, b0); b1 = fmaf(hb.z, w2.y, b1);
            a0 = fmaf(ha.w, w3.x, a0); a1 = fmaf(ha.w, w3.y, a1);
            b0 = fmaf(hb.w, w3.x, b0); b1 = fmaf(hb.w, w3.y, b1);
        }
        *(float2*)(out_sc + (size_t)(tbase + tlA) * SSC + c2) = make_float2(a0, a1);
        *(float2*)(out_sc + (size_t)(tbase + tlB) * SSC + c2) = make_float2(b0, b1);
    }
}

// ---------------------------------------------------------------------------
extern "C" void kernel_launch(void* const* d_in, const int* in_sizes, int n_in,
                              void* d_out, int out_size)
{
    const float* mv_src   = (const float*)d_in[0];
    const float* mv_skip  = (const float*)d_in[1];
    const float* sc_src   = (const float*)d_in[2];
    const float* sc_skip  = (const float*)d_in[3];
    const float* pos_src  = (const float*)d_in[4];
    const float* pos_tgt  = (const float*)d_in[5];
    const int*   isrc     = (const int*)d_in[6];
    const float* W1_mv    = (const float*)d_in[8];
    const float* W2_mv    = (const float*)d_in[9];
    const float* W1_s     = (const float*)d_in[10];
    const float* b1_s     = (const float*)d_in[11];
    const float* W2_s     = (const float*)d_in[12];
    const float* b2_s     = (const float*)d_in[13];

    float* out_mv = (float*)d_out;
    float* out_sc = out_mv + (size_t)N_TGT * CCH * MVD;

    prep_weff<<<1, 288>>>(W1_mv, W2_mv);
    fused_kernel<<<N_TGT / TGT_PER_BLOCK, TPB>>>(
        mv_src, mv_skip, sc_src, sc_skip, pos_src, pos_tgt, isrc,
        W1_s, b1_s, W2_s, b2_s, out_mv, out_sc);
}